// round 5
// baseline (speedup 1.0000x reference)
#include <cuda_runtime.h>
#include <mma.h>
#include <cstdint>

using namespace nvcuda;

#define FDIM 128
#define MAXN 200704

// Scratch (device globals; no allocation allowed)
__device__ float g_buf0[MAXN * FDIM];   // xw (GEMM output, pre-aggregation)
__device__ float g_buf1[MAXN * FDIM];   // layer-1 aggregation target / layer-2 GEMM input
__device__ float g_buf2[MAXN * FDIM];   // layer-2 aggregation target
__device__ float g_deg[MAXN];
__device__ float g_dinv[MAXN];
__device__ float g_sum[FDIM];
__device__ float g_sumsq[FDIM];
__device__ float g_W1p[FDIM * FDIM];    // W1 / sigma  (standardization folded)
__device__ float g_c1[FDIM];            // -(mu/sigma) @ W1
__device__ int   g_ei64;                // edge_index is int64?
__device__ int   g_b64;                 // batch is int64?

// ---------------------------------------------------------------------------
// Index accessors: dtype decided at runtime by device flag.
__device__ __forceinline__ int load_idx(const void* p, long long e, int is64) {
    return is64 ? (int)((const long long*)p)[e] : ((const int*)p)[e];
}

// Detect whether int-typed inputs are int64 or int32 by inspecting raw words.
// int64 little-endian values < 2^31 have ALL odd 32-bit words == 0.
__global__ void detect_dtype(const int* ei_w, int E, const int* b_w, int N) {
    if (threadIdx.x != 0 || blockIdx.x != 0) return;
    // edge_index: first 2048 words are within bounds for both dtypes
    // (int32 buffer has 2E words). Random indices -> odd words nonzero if int32.
    int nz = 0;
    int lim = 2 * E < 2048 ? 2 * E : 2048;
    for (int i = 1; i < lim; i += 2) nz += (ei_w[i] != 0);
    g_ei64 = (nz == 0) ? 1 : 0;
    // batch: sorted 0..G-1, so the FRONT is all zeros either way. Probe the
    // end of the first N words (valid for both dtypes). int32 -> words there
    // hold value G-1 != 0; int64 -> odd words are high halves == 0.
    int nzb = 0;
    for (int i = N - 1; i >= N - 2048 && i >= 0; i -= 2) {
        int odd = i | 1;                 // odd position
        if (odd < N) nzb += (b_w[odd] != 0);
    }
    g_b64 = (nzb == 0) ? 1 : 0;
}

__global__ void zero_kernel(float* __restrict__ dout, int outN, int N) {
    int i = blockIdx.x * blockDim.x + threadIdx.x;
    if (i < N)    g_deg[i] = 0.f;
    if (i < outN) dout[i] = 0.f;
    if (i < FDIM) { g_sum[i] = 0.f; g_sumsq[i] = 0.f; }
}

// Column sums / sums of squares of x (row-major [N,128]); coalesced.
__global__ void col_stats(const float* __restrict__ x, int N) {
    int col = threadIdx.x;  // blockDim = 128
    float s = 0.f, s2 = 0.f;
    for (int r = blockIdx.x; r < N; r += gridDim.x) {
        float v = x[(size_t)r * FDIM + col];
        s += v; s2 += v * v;
    }
    atomicAdd(&g_sum[col], s);
    atomicAdd(&g_sumsq[col], s2);
}

__global__ void deg_count(const void* __restrict__ ei, int E) {
    int e = blockIdx.x * blockDim.x + threadIdx.x;
    if (e < E) {
        int d = load_idx(ei, (long long)E + e, g_ei64);  // dst row of [2,E]
        atomicAdd(&g_deg[d], 1.0f);
    }
}

__global__ void dinv_kernel(int N) {
    int i = blockIdx.x * blockDim.x + threadIdx.x;
    if (i < N) g_dinv[i] = rsqrtf(g_deg[i] + 1.0f);
}

// Fold standardization into W1:  x_std @ W1 = x @ (W1/sigma) + c
__global__ void prep_kernel(const float* __restrict__ W1, int N) {
    __shared__ float mu[FDIM], isd[FDIM];
    int t = threadIdx.x;  // 128 threads
    float sum = g_sum[t];
    float mean = sum / (float)N;
    float var = (g_sumsq[t] - sum * mean) / (float)(N - 1);  // ddof=1
    mu[t] = mean;
    isd[t] = rsqrtf(var);
    __syncthreads();
    float c = 0.f;
    for (int f = 0; f < FDIM; f++) {
        float w = W1[f * FDIM + t];
        g_W1p[f * FDIM + t] = w * isd[f];
        c -= mu[f] * isd[f] * w;
    }
    g_c1[t] = c;
}

// ---------------------------------------------------------------------------
// GEMM: C[M,128] = A[M,128] @ B[128,128]  (tf32 wmma, K=128 in smem)
// Epilogue writes BOTH:
//   Cxw  = A@B (+ cvec)                       -> gathered by edge scatter
//   Cout = Cxw * dinv[row]^2 + bias[col]      -> self-loop + bias init
// RELU_A: apply relu to A on load (layer-2 input is relu(h1)).
template <bool RELU_A, bool ADD_C>
__global__ void gemm_kernel(const float* __restrict__ A, const float* __restrict__ B,
                            const float* __restrict__ cvec, const float* __restrict__ bias,
                            float* __restrict__ Cxw, float* __restrict__ Cout, int M)
{
    extern __shared__ float sB[];  // 128*128 floats = 64 KB (reused as epilogue stage)
    for (int i = threadIdx.x; i < FDIM * FDIM; i += blockDim.x)
        sB[i] = wmma::__float_to_tf32(B[i]);   // pre-round B to tf32 (RN)
    __syncthreads();

    int warp = threadIdx.x >> 5;
    int lane = threadIdx.x & 31;
    int row0 = blockIdx.x * 128 + warp * 16;
    bool active = (row0 + 16) <= M;   // full 16-row tiles only (M % 16 == 0 here)

    wmma::fragment<wmma::accumulator, 16, 16, 8, float> acc[8];
    if (active) {
#pragma unroll
        for (int n = 0; n < 8; n++) wmma::fill_fragment(acc[n], 0.f);
#pragma unroll
        for (int k = 0; k < FDIM; k += 8) {
            wmma::fragment<wmma::matrix_a, 16, 16, 8, wmma::precision::tf32, wmma::row_major> a;
            wmma::load_matrix_sync(a, A + (size_t)row0 * FDIM + k, FDIM);
#pragma unroll
            for (int t = 0; t < a.num_elements; t++) {
                float v = a.x[t];
                if (RELU_A) v = fmaxf(v, 0.f);
                a.x[t] = wmma::__float_to_tf32(v);
            }
#pragma unroll
            for (int n = 0; n < 8; n++) {
                wmma::fragment<wmma::matrix_b, 16, 16, 8, wmma::precision::tf32, wmma::row_major> b;
                wmma::load_matrix_sync(b, sB + k * FDIM + n * 16, FDIM);
                wmma::mma_sync(acc[n], a, b, acc[n]);
            }
        }
    }
    __syncthreads();  // all warps done reading sB before reuse as stage
    if (active) {
        float* stage = sB + warp * 16 * FDIM;
#pragma unroll
        for (int n = 0; n < 8; n++)
            wmma::store_matrix_sync(stage + n * 16, acc[n], FDIM, wmma::mem_row_major);
        __syncwarp();
        for (int i = lane; i < 16 * FDIM; i += 32) {
            int r = i >> 7;
            int c = i & 127;
            int grow = row0 + r;
            float v = stage[i];
            if (ADD_C) v += cvec[c];
            Cxw[(size_t)grow * FDIM + c] = v;
            float di = g_dinv[grow];
            Cout[(size_t)grow * FDIM + c] = v * di * di + bias[c];
        }
    }
}

// ---------------------------------------------------------------------------
__device__ __forceinline__ void red_add_v4(float* p, float4 v) {
    asm volatile("red.global.add.v4.f32 [%0], {%1, %2, %3, %4};"
                 :: "l"(p), "f"(v.x), "f"(v.y), "f"(v.z), "f"(v.w) : "memory");
}

// One warp per edge: gather xw[src] (512 B), scale, vector-reduce into out[dst].
__global__ void edge_scatter(const float* __restrict__ xw, float* __restrict__ out,
                             const void* __restrict__ ei, int E)
{
    int gw = (int)((blockIdx.x * (unsigned)blockDim.x + threadIdx.x) >> 5);
    int lane = threadIdx.x & 31;
    if (gw >= E) return;
    int is64 = g_ei64;
    int s = load_idx(ei, gw, is64);
    int d = load_idx(ei, (long long)E + gw, is64);
    float coef = g_dinv[s] * g_dinv[d];
    float4 v = ((const float4*)(xw + (size_t)s * FDIM))[lane];
    v.x *= coef; v.y *= coef; v.z *= coef; v.w *= coef;
    red_add_v4(out + (size_t)d * FDIM + lane * 4, v);
}

// One warp per node: relu + segment-sum into d_out[batch[node]].
__global__ void pool_kernel(const float* __restrict__ h, const void* __restrict__ batch,
                            float* __restrict__ dout, int N)
{
    int node = (int)((blockIdx.x * (unsigned)blockDim.x + threadIdx.x) >> 5);
    int lane = threadIdx.x & 31;
    if (node >= N) return;
    int g = load_idx(batch, node, g_b64);
    float4 v = ((const float4*)(h + (size_t)node * FDIM))[lane];
    v.x = fmaxf(v.x, 0.f); v.y = fmaxf(v.y, 0.f);
    v.z = fmaxf(v.z, 0.f); v.w = fmaxf(v.w, 0.f);
    red_add_v4(dout + g * FDIM + lane * 4, v);
}

// ---------------------------------------------------------------------------
extern "C" void kernel_launch(void* const* d_in, const int* in_sizes, int n_in,
                              void* d_out, int out_size)
{
    // Fixed positions: x, edge_index, batch are always the first three.
    const float* x     = (const float*)d_in[0];
    const void*  ei    = d_in[1];          // [2,E], int32 or int64 (detected on device)
    const void*  batch = d_in[2];

    int N = in_sizes[0] / FDIM;
    int E = in_sizes[1] / 2;

    // Resolve W1,b1,W2,b2 by element count; skip scalar-sized entries
    // (num_graphs may or may not be materialized as an input).
    const float* wb[4] = {nullptr, nullptr, nullptr, nullptr};
    const int want[4] = {FDIM * FDIM, FDIM, FDIM * FDIM, FDIM};
    int slot = 0;
    for (int i = 3; i < n_in && slot < 4; i++) {
        if (in_sizes[i] <= 2) continue;            // scalar (num_graphs)
        if (in_sizes[i] == want[slot]) wb[slot++] = (const float*)d_in[i];
    }
    if (slot < 4 && n_in >= 7) {                   // fallback: last four inputs
        for (int k = 0; k < 4; k++) wb[k] = (const float*)d_in[n_in - 4 + k];
    }
    const float* W1 = wb[0];
    const float* b1 = wb[1];
    const float* W2 = wb[2];
    const float* b2 = wb[3];

    float* out = (float*)d_out;

    float *p0, *p1, *p2, *pW1p, *pc1;
    cudaGetSymbolAddress((void**)&p0,   g_buf0);
    cudaGetSymbolAddress((void**)&p1,   g_buf1);
    cudaGetSymbolAddress((void**)&p2,   g_buf2);
    cudaGetSymbolAddress((void**)&pW1p, g_W1p);
    cudaGetSymbolAddress((void**)&pc1,  g_c1);

    const int SMEM = FDIM * FDIM * sizeof(float);  // 64 KB
    cudaFuncSetAttribute(gemm_kernel<false, true>,
                         cudaFuncAttributeMaxDynamicSharedMemorySize, SMEM);
    cudaFuncSetAttribute(gemm_kernel<true, false>,
                         cudaFuncAttributeMaxDynamicSharedMemorySize, SMEM);

    detect_dtype<<<1, 32>>>((const int*)ei, E, (const int*)batch, N);
    zero_kernel<<<(N + 255) / 256, 256>>>(out, out_size, N);
    col_stats<<<1024, 128>>>(x, N);
    deg_count<<<(E + 255) / 256, 256>>>(ei, E);
    dinv_kernel<<<(N + 255) / 256, 256>>>(N);
    prep_kernel<<<1, 128>>>(W1, N);

    int gblocks = (N + 127) / 128;
    int eblocks = (E + 7) / 8;  // 8 warps (edges) per 256-thread block
    int nblocks = (N + 7) / 8;

    // Layer 1: xw1 = x @ W1' + c1  -> buf0 ; buf1 = xw1*dinv^2 + b1
    gemm_kernel<false, true><<<gblocks, 256, SMEM>>>(x, pW1p, pc1, b1, p0, p1, N);
    edge_scatter<<<eblocks, 256>>>(p0, p1, ei, E);

    // Layer 2: xw2 = relu(h1) @ W2 -> buf0 ; buf2 = xw2*dinv^2 + b2
    gemm_kernel<true, false><<<gblocks, 256, SMEM>>>(p1, W2, nullptr, b2, p0, p2, N);
    edge_scatter<<<eblocks, 256>>>(p0, p2, ei, E);

    // Pool: out[g] += relu(h2[node])
    pool_kernel<<<nblocks, 256>>>(p2, batch, out, N);
}

// round 6
// speedup vs baseline: 1.1049x; 1.1049x over previous
#include <cuda_runtime.h>
#include <mma.h>
#include <cstdint>

using namespace nvcuda;

#define FDIM 128
#define MAXN 200704
#define MAXE 602112
#define MAXB 256          // max scan blocks (256*1024 >= MAXN)

// Scratch (device globals; no allocation allowed)
__device__ float g_buf0[MAXN * FDIM];   // xw (GEMM output, pre-aggregation)
__device__ float g_buf1[MAXN * FDIM];   // layer-1 aggregated h1 (layer-2 GEMM input)
__device__ int   g_degi[MAXN];
__device__ float g_dinv[MAXN];
__device__ int   g_rowp[MAXN + 1];
__device__ int   g_cursor[MAXN];
__device__ int   g_bsum[MAXB];
__device__ int   g_boff[MAXB];
__device__ int   g_esrc[MAXE];
__device__ float g_ecoef[MAXE];
__device__ float g_sum[FDIM];
__device__ float g_sumsq[FDIM];
__device__ float g_W1p[FDIM * FDIM];    // W1 / sigma  (standardization folded)
__device__ float g_c1[FDIM];            // -(mu/sigma) @ W1
__device__ int   g_ei64;                // edge_index is int64?
__device__ int   g_b64;                 // batch is int64?

// ---------------------------------------------------------------------------
__device__ __forceinline__ int load_idx(const void* p, long long e, int is64) {
    return is64 ? (int)((const long long*)p)[e] : ((const int*)p)[e];
}

// Detect int64 vs int32 by inspecting raw 32-bit words (values < 2^31 ->
// int64 little-endian has all odd words zero).
__global__ void detect_dtype(const int* ei_w, int E, const int* b_w, int N) {
    if (threadIdx.x != 0 || blockIdx.x != 0) return;
    int nz = 0;
    int lim = 2 * E < 2048 ? 2 * E : 2048;
    for (int i = 1; i < lim; i += 2) nz += (ei_w[i] != 0);
    g_ei64 = (nz == 0) ? 1 : 0;
    int nzb = 0;
    for (int i = N - 1; i >= N - 2048 && i >= 0; i -= 2) {
        int odd = i | 1;
        if (odd < N) nzb += (b_w[odd] != 0);
    }
    g_b64 = (nzb == 0) ? 1 : 0;
}

__global__ void zero_kernel(float* __restrict__ dout, int outN, int N) {
    int i = blockIdx.x * blockDim.x + threadIdx.x;
    if (i < N)    { g_degi[i] = 0; g_cursor[i] = 0; }
    if (i < outN) dout[i] = 0.f;
    if (i < FDIM) { g_sum[i] = 0.f; g_sumsq[i] = 0.f; }
}

// Column sums / sums of squares of x (row-major [N,128]); coalesced.
__global__ void col_stats(const float* __restrict__ x, int N) {
    int col = threadIdx.x;  // blockDim = 128
    float s = 0.f, s2 = 0.f;
    for (int r = blockIdx.x; r < N; r += gridDim.x) {
        float v = x[(size_t)r * FDIM + col];
        s += v; s2 += v * v;
    }
    atomicAdd(&g_sum[col], s);
    atomicAdd(&g_sumsq[col], s2);
}

__global__ void deg_count(const void* __restrict__ ei, int E) {
    int e = blockIdx.x * blockDim.x + threadIdx.x;
    if (e < E) {
        int d = load_idx(ei, (long long)E + e, g_ei64);
        atomicAdd(&g_degi[d], 1);
    }
}

__global__ void dinv_kernel(int N) {
    int i = blockIdx.x * blockDim.x + threadIdx.x;
    if (i < N) g_dinv[i] = rsqrtf((float)g_degi[i] + 1.0f);
}

// Fold standardization into W1:  x_std @ W1 = x @ (W1/sigma) + c
__global__ void prep_kernel(const float* __restrict__ W1, int N) {
    __shared__ float mu[FDIM], isd[FDIM];
    int t = threadIdx.x;  // 128 threads
    float sum = g_sum[t];
    float mean = sum / (float)N;
    float var = (g_sumsq[t] - sum * mean) / (float)(N - 1);  // ddof=1
    mu[t] = mean;
    isd[t] = rsqrtf(var);
    __syncthreads();
    float c = 0.f;
    for (int f = 0; f < FDIM; f++) {
        float w = W1[f * FDIM + t];
        g_W1p[f * FDIM + t] = w * isd[f];
        c -= mu[f] * isd[f] * w;
    }
    g_c1[t] = c;
}

// ---------------------------------------------------------------------------
// CSR build: exclusive prefix sum of g_degi -> g_rowp, then bin edges.
// scan1: per-block (1024 items) local exclusive scan + block totals.
__global__ void scan1(int N) {
    __shared__ int sh[256];
    int t = threadIdx.x;
    int base = blockIdx.x * 1024 + t * 4;
    int v[4]; int s = 0;
#pragma unroll
    for (int i = 0; i < 4; i++) {
        v[i] = (base + i < N) ? g_degi[base + i] : 0;
        s += v[i];
    }
    sh[t] = s; __syncthreads();
    for (int off = 1; off < 256; off <<= 1) {
        int x = (t >= off) ? sh[t - off] : 0;
        __syncthreads();
        sh[t] += x;
        __syncthreads();
    }
    int run = sh[t] - s;   // exclusive
    if (t == 255) g_bsum[blockIdx.x] = sh[255];
#pragma unroll
    for (int i = 0; i < 4; i++) {
        if (base + i < N) { g_rowp[base + i] = run; run += v[i]; }
    }
}

// scan2: exclusive scan of up to 256 block totals (single block).
__global__ void scan2(int NB) {
    __shared__ int sh[256];
    int t = threadIdx.x;
    int v = (t < NB) ? g_bsum[t] : 0;
    sh[t] = v; __syncthreads();
    for (int off = 1; off < 256; off <<= 1) {
        int x = (t >= off) ? sh[t - off] : 0;
        __syncthreads();
        sh[t] += x;
        __syncthreads();
    }
    if (t < NB) g_boff[t] = sh[t] - v;
}

// scan3: add block offsets; finalize rowp[N] = E.
__global__ void scan3(int N, int E) {
    int i = blockIdx.x * blockDim.x + threadIdx.x;
    if (i < N) g_rowp[i] += g_boff[i >> 10];
    if (i == 0) g_rowp[N] = E;
}

__global__ void bin_edges(const void* __restrict__ ei, int E) {
    int e = blockIdx.x * blockDim.x + threadIdx.x;
    if (e >= E) return;
    int is64 = g_ei64;
    int s = load_idx(ei, e, is64);
    int d = load_idx(ei, (long long)E + e, is64);
    int pos = g_rowp[d] + atomicAdd(&g_cursor[d], 1);
    g_esrc[pos] = s;
    g_ecoef[pos] = g_dinv[s] * g_dinv[d];
}

// ---------------------------------------------------------------------------
// GEMM: C[M,128] = A[M,128] @ B[128,128]  (tf32 wmma, K=128 in smem).
// Writes only Cxw (+cvec). RELU_A: relu applied to A on load (layer 2).
template <bool RELU_A, bool ADD_C>
__global__ void gemm_kernel(const float* __restrict__ A, const float* __restrict__ B,
                            const float* __restrict__ cvec,
                            float* __restrict__ Cxw, int M)
{
    extern __shared__ float sB[];  // 128*128 floats = 64 KB (reused as epilogue stage)
    for (int i = threadIdx.x; i < FDIM * FDIM; i += blockDim.x)
        sB[i] = wmma::__float_to_tf32(B[i]);
    __syncthreads();

    int warp = threadIdx.x >> 5;
    int lane = threadIdx.x & 31;
    int row0 = blockIdx.x * 128 + warp * 16;
    bool active = (row0 + 16) <= M;

    wmma::fragment<wmma::accumulator, 16, 16, 8, float> acc[8];
    if (active) {
#pragma unroll
        for (int n = 0; n < 8; n++) wmma::fill_fragment(acc[n], 0.f);
#pragma unroll
        for (int k = 0; k < FDIM; k += 8) {
            wmma::fragment<wmma::matrix_a, 16, 16, 8, wmma::precision::tf32, wmma::row_major> a;
            wmma::load_matrix_sync(a, A + (size_t)row0 * FDIM + k, FDIM);
#pragma unroll
            for (int t = 0; t < a.num_elements; t++) {
                float v = a.x[t];
                if (RELU_A) v = fmaxf(v, 0.f);
                a.x[t] = wmma::__float_to_tf32(v);
            }
#pragma unroll
            for (int n = 0; n < 8; n++) {
                wmma::fragment<wmma::matrix_b, 16, 16, 8, wmma::precision::tf32, wmma::row_major> b;
                wmma::load_matrix_sync(b, sB + k * FDIM + n * 16, FDIM);
                wmma::mma_sync(acc[n], a, b, acc[n]);
            }
        }
    }
    __syncthreads();
    if (active) {
        float* stage = sB + warp * 16 * FDIM;
#pragma unroll
        for (int n = 0; n < 8; n++)
            wmma::store_matrix_sync(stage + n * 16, acc[n], FDIM, wmma::mem_row_major);
        __syncwarp();
        for (int i = lane; i < 16 * FDIM; i += 32) {
            int c = i & 127;
            float v = stage[i];
            if (ADD_C) v += cvec[c];
            Cxw[(size_t)(row0 + (i >> 7)) * FDIM + c] = v;
        }
    }
}

// ---------------------------------------------------------------------------
__device__ __forceinline__ void red_add_v4(float* p, float4 v) {
    asm volatile("red.global.add.v4.f32 [%0], {%1, %2, %3, %4};"
                 :: "l"(p), "f"(v.x), "f"(v.y), "f"(v.z), "f"(v.w) : "memory");
}

// Atomic-free segmented aggregation: one warp owns one dst node's full row.
//   h[d] = sum_{e in seg(d)} coef[e]*xw[src[e]] + dinv[d]^2*xw[d] + bias
// POOL=false: write h to out[d] (layer 1).
// POOL=true:  out[batch[d]] += relu(h)  (layer 2 fused with global_add_pool).
template <bool POOL>
__global__ void aggregate(const float* __restrict__ xw, float* __restrict__ out,
                          const float* __restrict__ bias,
                          const void* __restrict__ batch, int N)
{
    int node = (int)((blockIdx.x * (unsigned)blockDim.x + threadIdx.x) >> 5);
    int lane = threadIdx.x & 31;
    if (node >= N) return;
    int beg = g_rowp[node];
    int end = g_rowp[node + 1];
    float4 acc = make_float4(0.f, 0.f, 0.f, 0.f);
    for (int e = beg; e < end; e++) {
        int s = g_esrc[e];
        float c = g_ecoef[e];
        float4 v = __ldg((const float4*)(xw + (size_t)s * FDIM) + lane);
        acc.x += c * v.x; acc.y += c * v.y; acc.z += c * v.z; acc.w += c * v.w;
    }
    float di = g_dinv[node];
    float sc = di * di;
    float4 v = ((const float4*)(xw + (size_t)node * FDIM))[lane];
    float4 b = ((const float4*)bias)[lane];
    acc.x += sc * v.x + b.x;
    acc.y += sc * v.y + b.y;
    acc.z += sc * v.z + b.z;
    acc.w += sc * v.w + b.w;
    if (POOL) {
        acc.x = fmaxf(acc.x, 0.f); acc.y = fmaxf(acc.y, 0.f);
        acc.z = fmaxf(acc.z, 0.f); acc.w = fmaxf(acc.w, 0.f);
        int g = load_idx(batch, node, g_b64);
        red_add_v4(out + (size_t)g * FDIM + lane * 4, acc);
    } else {
        ((float4*)(out + (size_t)node * FDIM))[lane] = acc;
    }
}

// ---------------------------------------------------------------------------
extern "C" void kernel_launch(void* const* d_in, const int* in_sizes, int n_in,
                              void* d_out, int out_size)
{
    const float* x     = (const float*)d_in[0];
    const void*  ei    = d_in[1];          // [2,E], int32 or int64 (device-detected)
    const void*  batch = d_in[2];

    int N = in_sizes[0] / FDIM;
    int E = in_sizes[1] / 2;

    const float* wb[4] = {nullptr, nullptr, nullptr, nullptr};
    const int want[4] = {FDIM * FDIM, FDIM, FDIM * FDIM, FDIM};
    int slot = 0;
    for (int i = 3; i < n_in && slot < 4; i++) {
        if (in_sizes[i] <= 2) continue;
        if (in_sizes[i] == want[slot]) wb[slot++] = (const float*)d_in[i];
    }
    if (slot < 4 && n_in >= 7) {
        for (int k = 0; k < 4; k++) wb[k] = (const float*)d_in[n_in - 4 + k];
    }
    const float* W1 = wb[0];
    const float* b1 = wb[1];
    const float* W2 = wb[2];
    const float* b2 = wb[3];

    float* out = (float*)d_out;

    float *p0, *p1, *pW1p, *pc1;
    cudaGetSymbolAddress((void**)&p0,   g_buf0);
    cudaGetSymbolAddress((void**)&p1,   g_buf1);
    cudaGetSymbolAddress((void**)&pW1p, g_W1p);
    cudaGetSymbolAddress((void**)&pc1,  g_c1);

    const int SMEM = FDIM * FDIM * sizeof(float);  // 64 KB
    cudaFuncSetAttribute(gemm_kernel<false, true>,
                         cudaFuncAttributeMaxDynamicSharedMemorySize, SMEM);
    cudaFuncSetAttribute(gemm_kernel<true, false>,
                         cudaFuncAttributeMaxDynamicSharedMemorySize, SMEM);

    detect_dtype<<<1, 32>>>((const int*)ei, E, (const int*)batch, N);
    zero_kernel<<<(N + 255) / 256, 256>>>(out, out_size, N);
    col_stats<<<1024, 128>>>(x, N);
    deg_count<<<(E + 255) / 256, 256>>>(ei, E);
    dinv_kernel<<<(N + 255) / 256, 256>>>(N);
    prep_kernel<<<1, 128>>>(W1, N);

    // CSR build
    int NB = (N + 1023) / 1024;
    scan1<<<NB, 256>>>(N);
    scan2<<<1, 256>>>(NB);
    scan3<<<(N + 255) / 256, 256>>>(N, E);
    bin_edges<<<(E + 255) / 256, 256>>>(ei, E);

    int gblocks = (N + 127) / 128;
    int ablocks = (N + 7) / 8;   // 8 warps (nodes) per 256-thread block

    // Layer 1: xw1 = x @ W1' + c1 -> buf0 ; h1 = agg(xw1) + b1 -> buf1
    gemm_kernel<false, true><<<gblocks, 256, SMEM>>>(x, pW1p, pc1, p0, N);
    aggregate<false><<<ablocks, 256>>>(p0, p1, b1, batch, N);

    // Layer 2: xw2 = relu(h1) @ W2 -> buf0 ; out[batch] += relu(agg(xw2) + b2)
    gemm_kernel<true, false><<<gblocks, 256, SMEM>>>(p1, W2, nullptr, p0, N);
    aggregate<true><<<ablocks, 256>>>(p0, out, b2, batch, N);
}

// round 7
// speedup vs baseline: 1.1650x; 1.0544x over previous
#include <cuda_runtime.h>
#include <mma.h>
#include <cstdint>

using namespace nvcuda;

#define FDIM 128
#define BPAD 132          // padded smem row stride (floats): kills 8-way bank conflicts
#define MAXN 200704
#define MAXE 602112
#define MAXB 256          // max scan blocks (256*1024 >= MAXN)

// Scratch (device globals; no allocation allowed)
__device__ float g_buf0[MAXN * FDIM];   // xw (GEMM output, pre-aggregation)
__device__ float g_buf1[MAXN * FDIM];   // layer-1 aggregated h1 (layer-2 GEMM input)
__device__ int   g_degi[MAXN];
__device__ float g_dinv[MAXN];
__device__ int   g_rowp[MAXN + 1];
__device__ int   g_cursor[MAXN];
__device__ int   g_bsum[MAXB];
__device__ int   g_boff[MAXB];
__device__ int   g_esrc[MAXE];
__device__ float g_ecoef[MAXE];
__device__ float g_sum[FDIM];
__device__ float g_sumsq[FDIM];
__device__ float g_W1p[FDIM * FDIM];    // W1 / sigma  (standardization folded)
__device__ float g_c1[FDIM];            // -(mu/sigma) @ W1
__device__ int   g_ei64;                // edge_index is int64?
__device__ int   g_b64;                 // batch is int64?

// ---------------------------------------------------------------------------
__device__ __forceinline__ int load_idx(const void* p, long long e, int is64) {
    return is64 ? (int)((const long long*)p)[e] : ((const int*)p)[e];
}

// Detect int64 vs int32 by inspecting raw 32-bit words (values < 2^31 ->
// int64 little-endian has all odd words zero).
__global__ void detect_dtype(const int* ei_w, int E, const int* b_w, int N) {
    if (threadIdx.x != 0 || blockIdx.x != 0) return;
    int nz = 0;
    int lim = 2 * E < 2048 ? 2 * E : 2048;
    for (int i = 1; i < lim; i += 2) nz += (ei_w[i] != 0);
    g_ei64 = (nz == 0) ? 1 : 0;
    int nzb = 0;
    for (int i = N - 1; i >= N - 2048 && i >= 0; i -= 2) {
        int odd = i | 1;
        if (odd < N) nzb += (b_w[odd] != 0);
    }
    g_b64 = (nzb == 0) ? 1 : 0;
}

__global__ void zero_kernel(float* __restrict__ dout, int outN, int N) {
    int i = blockIdx.x * blockDim.x + threadIdx.x;
    if (i < N)    { g_degi[i] = 0; g_cursor[i] = 0; }
    if (i < outN) dout[i] = 0.f;
    if (i < FDIM) { g_sum[i] = 0.f; g_sumsq[i] = 0.f; }
}

// Column sums / sums of squares of x (row-major [N,128]); coalesced.
__global__ void col_stats(const float* __restrict__ x, int N) {
    int col = threadIdx.x;  // blockDim = 128
    float s = 0.f, s2 = 0.f;
    for (int r = blockIdx.x; r < N; r += gridDim.x) {
        float v = x[(size_t)r * FDIM + col];
        s += v; s2 += v * v;
    }
    atomicAdd(&g_sum[col], s);
    atomicAdd(&g_sumsq[col], s2);
}

__global__ void deg_count(const void* __restrict__ ei, int E) {
    int e = blockIdx.x * blockDim.x + threadIdx.x;
    if (e < E) {
        int d = load_idx(ei, (long long)E + e, g_ei64);
        atomicAdd(&g_degi[d], 1);
    }
}

__global__ void dinv_kernel(int N) {
    int i = blockIdx.x * blockDim.x + threadIdx.x;
    if (i < N) g_dinv[i] = rsqrtf((float)g_degi[i] + 1.0f);
}

// Fold standardization into W1:  x_std @ W1 = x @ (W1/sigma) + c
__global__ void prep_kernel(const float* __restrict__ W1, int N) {
    __shared__ float mu[FDIM], isd[FDIM];
    int t = threadIdx.x;  // 128 threads
    float sum = g_sum[t];
    float mean = sum / (float)N;
    float var = (g_sumsq[t] - sum * mean) / (float)(N - 1);  // ddof=1
    mu[t] = mean;
    isd[t] = rsqrtf(var);
    __syncthreads();
    float c = 0.f;
    for (int f = 0; f < FDIM; f++) {
        float w = W1[f * FDIM + t];
        g_W1p[f * FDIM + t] = w * isd[f];
        c -= mu[f] * isd[f] * w;
    }
    g_c1[t] = c;
}

// ---------------------------------------------------------------------------
// CSR build: exclusive prefix sum of g_degi -> g_rowp, then bin edges.
__global__ void scan1(int N) {
    __shared__ int sh[256];
    int t = threadIdx.x;
    int base = blockIdx.x * 1024 + t * 4;
    int v[4]; int s = 0;
#pragma unroll
    for (int i = 0; i < 4; i++) {
        v[i] = (base + i < N) ? g_degi[base + i] : 0;
        s += v[i];
    }
    sh[t] = s; __syncthreads();
    for (int off = 1; off < 256; off <<= 1) {
        int x = (t >= off) ? sh[t - off] : 0;
        __syncthreads();
        sh[t] += x;
        __syncthreads();
    }
    int run = sh[t] - s;   // exclusive
    if (t == 255) g_bsum[blockIdx.x] = sh[255];
#pragma unroll
    for (int i = 0; i < 4; i++) {
        if (base + i < N) { g_rowp[base + i] = run; run += v[i]; }
    }
}

__global__ void scan2(int NB) {
    __shared__ int sh[256];
    int t = threadIdx.x;
    int v = (t < NB) ? g_bsum[t] : 0;
    sh[t] = v; __syncthreads();
    for (int off = 1; off < 256; off <<= 1) {
        int x = (t >= off) ? sh[t - off] : 0;
        __syncthreads();
        sh[t] += x;
        __syncthreads();
    }
    if (t < NB) g_boff[t] = sh[t] - v;
}

__global__ void scan3(int N, int E) {
    int i = blockIdx.x * blockDim.x + threadIdx.x;
    if (i < N) g_rowp[i] += g_boff[i >> 10];
    if (i == 0) g_rowp[N] = E;
}

__global__ void bin_edges(const void* __restrict__ ei, int E) {
    int e = blockIdx.x * blockDim.x + threadIdx.x;
    if (e >= E) return;
    int is64 = g_ei64;
    int s = load_idx(ei, e, is64);
    int d = load_idx(ei, (long long)E + e, is64);
    int pos = g_rowp[d] + atomicAdd(&g_cursor[d], 1);
    g_esrc[pos] = s;
    g_ecoef[pos] = g_dinv[s] * g_dinv[d];
}

// ---------------------------------------------------------------------------
// GEMM: C[M,128] = A[M,128] @ B[128,128]  (tf32 wmma, K=128 in padded smem).
// Writes only Cxw (+cvec). RELU_A: relu applied to A on load (layer 2).
template <bool RELU_A, bool ADD_C>
__global__ void gemm_kernel(const float* __restrict__ A, const float* __restrict__ B,
                            const float* __restrict__ cvec,
                            float* __restrict__ Cxw, int M)
{
    extern __shared__ float sB[];  // 128*BPAD floats (reused as epilogue stage)
    for (int i = threadIdx.x; i < FDIM * FDIM; i += blockDim.x) {
        int r = i >> 7, c = i & 127;
        sB[r * BPAD + c] = wmma::__float_to_tf32(B[i]);
    }
    __syncthreads();

    int warp = threadIdx.x >> 5;
    int lane = threadIdx.x & 31;
    int row0 = blockIdx.x * 128 + warp * 16;
    bool active = (row0 + 16) <= M;

    wmma::fragment<wmma::accumulator, 16, 16, 8, float> acc[8];
    if (active) {
#pragma unroll
        for (int n = 0; n < 8; n++) wmma::fill_fragment(acc[n], 0.f);
#pragma unroll
        for (int k = 0; k < FDIM; k += 8) {
            wmma::fragment<wmma::matrix_a, 16, 16, 8, wmma::precision::tf32, wmma::row_major> a;
            wmma::load_matrix_sync(a, A + (size_t)row0 * FDIM + k, FDIM);
#pragma unroll
            for (int t = 0; t < a.num_elements; t++) {
                float v = a.x[t];
                if (RELU_A) v = fmaxf(v, 0.f);
                a.x[t] = wmma::__float_to_tf32(v);
            }
#pragma unroll
            for (int n = 0; n < 8; n++) {
                wmma::fragment<wmma::matrix_b, 16, 16, 8, wmma::precision::tf32, wmma::row_major> b;
                wmma::load_matrix_sync(b, sB + k * BPAD + n * 16, BPAD);
                wmma::mma_sync(acc[n], a, b, acc[n]);
            }
        }
    }
    __syncthreads();
    if (active) {
        float* stage = sB + warp * 16 * BPAD;
#pragma unroll
        for (int n = 0; n < 8; n++)
            wmma::store_matrix_sync(stage + n * 16, acc[n], BPAD, wmma::mem_row_major);
        __syncwarp();
        for (int i = lane; i < 16 * FDIM; i += 32) {
            int r = i >> 7;
            int c = i & 127;
            float v = stage[r * BPAD + c];
            if (ADD_C) v += cvec[c];
            Cxw[(size_t)(row0 + r) * FDIM + c] = v;
        }
    }
}

// ---------------------------------------------------------------------------
__device__ __forceinline__ void red_add_v4(float* p, float4 v) {
    asm volatile("red.global.add.v4.f32 [%0], {%1, %2, %3, %4};"
                 :: "l"(p), "f"(v.x), "f"(v.y), "f"(v.z), "f"(v.w) : "memory");
}

// Atomic-free segmented aggregation: one warp owns one dst node's full row.
//   h[d] = sum_{e in seg(d)} coef[e]*xw[src[e]] + dinv[d]^2*xw[d] + bias
// POOL=false: write h to out[d] (layer 1).
// POOL=true:  out[batch[d]] += relu(h)  (layer 2 fused with global_add_pool).
template <bool POOL>
__global__ void aggregate(const float* __restrict__ xw, float* __restrict__ out,
                          const float* __restrict__ bias,
                          const void* __restrict__ batch, int N)
{
    int node = (int)((blockIdx.x * (unsigned)blockDim.x + threadIdx.x) >> 5);
    int lane = threadIdx.x & 31;
    if (node >= N) return;
    int beg = g_rowp[node];
    int end = g_rowp[node + 1];
    float4 acc = make_float4(0.f, 0.f, 0.f, 0.f);
    for (int e = beg; e < end; e++) {
        int s = g_esrc[e];
        float c = g_ecoef[e];
        float4 v = __ldg((const float4*)(xw + (size_t)s * FDIM) + lane);
        acc.x += c * v.x; acc.y += c * v.y; acc.z += c * v.z; acc.w += c * v.w;
    }
    float di = g_dinv[node];
    float sc = di * di;
    float4 v = ((const float4*)(xw + (size_t)node * FDIM))[lane];
    float4 b = ((const float4*)bias)[lane];
    acc.x += sc * v.x + b.x;
    acc.y += sc * v.y + b.y;
    acc.z += sc * v.z + b.z;
    acc.w += sc * v.w + b.w;
    if (POOL) {
        acc.x = fmaxf(acc.x, 0.f); acc.y = fmaxf(acc.y, 0.f);
        acc.z = fmaxf(acc.z, 0.f); acc.w = fmaxf(acc.w, 0.f);
        int g = load_idx(batch, node, g_b64);
        red_add_v4(out + (size_t)g * FDIM + lane * 4, acc);
    } else {
        ((float4*)(out + (size_t)node * FDIM))[lane] = acc;
    }
}

// ---------------------------------------------------------------------------
extern "C" void kernel_launch(void* const* d_in, const int* in_sizes, int n_in,
                              void* d_out, int out_size)
{
    const float* x     = (const float*)d_in[0];
    const void*  ei    = d_in[1];          // [2,E], int32 or int64 (device-detected)
    const void*  batch = d_in[2];

    int N = in_sizes[0] / FDIM;
    int E = in_sizes[1] / 2;

    const float* wb[4] = {nullptr, nullptr, nullptr, nullptr};
    const int want[4] = {FDIM * FDIM, FDIM, FDIM * FDIM, FDIM};
    int slot = 0;
    for (int i = 3; i < n_in && slot < 4; i++) {
        if (in_sizes[i] <= 2) continue;
        if (in_sizes[i] == want[slot]) wb[slot++] = (const float*)d_in[i];
    }
    if (slot < 4 && n_in >= 7) {
        for (int k = 0; k < 4; k++) wb[k] = (const float*)d_in[n_in - 4 + k];
    }
    const float* W1 = wb[0];
    const float* b1 = wb[1];
    const float* W2 = wb[2];
    const float* b2 = wb[3];

    float* out = (float*)d_out;

    float *p0, *p1, *pW1p, *pc1;
    cudaGetSymbolAddress((void**)&p0,   g_buf0);
    cudaGetSymbolAddress((void**)&p1,   g_buf1);
    cudaGetSymbolAddress((void**)&pW1p, g_W1p);
    cudaGetSymbolAddress((void**)&pc1,  g_c1);

    const int SMEM = FDIM * BPAD * sizeof(float);  // 66 KB (padded)
    cudaFuncSetAttribute(gemm_kernel<false, true>,
                         cudaFuncAttributeMaxDynamicSharedMemorySize, SMEM);
    cudaFuncSetAttribute(gemm_kernel<true, false>,
                         cudaFuncAttributeMaxDynamicSharedMemorySize, SMEM);

    detect_dtype<<<1, 32>>>((const int*)ei, E, (const int*)batch, N);
    zero_kernel<<<(N + 255) / 256, 256>>>(out, out_size, N);
    col_stats<<<1024, 128>>>(x, N);
    deg_count<<<(E + 255) / 256, 256>>>(ei, E);
    dinv_kernel<<<(N + 255) / 256, 256>>>(N);
    prep_kernel<<<1, 128>>>(W1, N);

    // CSR build
    int NB = (N + 1023) / 1024;
    scan1<<<NB, 256>>>(N);
    scan2<<<1, 256>>>(NB);
    scan3<<<(N + 255) / 256, 256>>>(N, E);
    bin_edges<<<(E + 255) / 256, 256>>>(ei, E);

    int gblocks = (N + 127) / 128;
    int ablocks = (N + 7) / 8;   // 8 warps (nodes) per 256-thread block

    // Layer 1: xw1 = x @ W1' + c1 -> buf0 ; h1 = agg(xw1) + b1 -> buf1
    gemm_kernel<false, true><<<gblocks, 256, SMEM>>>(x, pW1p, pc1, p0, N);
    aggregate<false><<<ablocks, 256>>>(p0, p1, b1, batch, N);

    // Layer 2: xw2 = relu(h1) @ W2 -> buf0 ; out[batch] += relu(agg(xw2) + b2)
    gemm_kernel<true, false><<<gblocks, 256, SMEM>>>(p1, W2, nullptr, p0, N);
    aggregate<true><<<ablocks, 256>>>(p0, out, b2, batch, N);
}

// round 8
// speedup vs baseline: 1.3179x; 1.1312x over previous
#include <cuda_runtime.h>
#include <mma.h>
#include <cstdint>

using namespace nvcuda;

#define FDIM 128
#define BPAD 132          // padded smem row stride (floats): kills 8-way bank conflicts
#define MAXN 200704
#define MAXE 602112
#define MAXB 256          // max scan blocks (256*1024 >= MAXN)

// Scratch (device globals; no allocation allowed)
__device__ float g_buf0[MAXN * FDIM];   // xw (GEMM output, pre-aggregation)
__device__ float g_buf1[MAXN * FDIM];   // layer-1 aggregated h1 (layer-2 GEMM input)
__device__ int   g_degi[MAXN];
__device__ float g_dinv[MAXN];
__device__ int   g_rowp[MAXN + 1];
__device__ int   g_cursor[MAXN];
__device__ int   g_bsum[MAXB];
__device__ int   g_boff[MAXB];
__device__ int   g_esrc[MAXE];
__device__ float g_ecoef[MAXE];
__device__ float g_sum[FDIM];
__device__ float g_sumsq[FDIM];
__device__ float g_W1p[FDIM * FDIM];    // W1 / sigma  (standardization folded)
__device__ float g_c1[FDIM];            // -(mu/sigma) @ W1
__device__ int   g_ei64;                // edge_index is int64?
__device__ int   g_b64;                 // batch is int64?

// ---------------------------------------------------------------------------
__device__ __forceinline__ int load_idx(const void* p, long long e, int is64) {
    return is64 ? (int)((const long long*)p)[e] : ((const int*)p)[e];
}

// Detect int64 vs int32 by inspecting raw 32-bit words (values < 2^31 ->
// int64 little-endian has all odd words zero). PARALLEL version: the old
// single-thread probe was ~2048 serial global loads (~650us!).
__global__ void detect_dtype(const int* ei_w, int E, const int* b_w, int N) {
    __shared__ int nz;
    if (threadIdx.x == 0) nz = 0;
    __syncthreads();
    if (blockIdx.x == 0) {
        // edge_index: odd words within first min(2E, 2048) words.
        int lim = 2 * E < 2048 ? 2 * E : 2048;
        for (int i = 1 + 2 * threadIdx.x; i < lim; i += 2 * blockDim.x)
            if (ei_w[i] != 0) atomicAdd(&nz, 1);
        __syncthreads();
        if (threadIdx.x == 0) g_ei64 = (nz == 0) ? 1 : 0;
    } else {
        // batch: odd positions within the last 2048 of the first N words
        // (front is all zeros for sorted batch ids regardless of dtype).
        int start = N - 2048; if (start < 0) start = 0;
        for (int i = start + threadIdx.x; i < N; i += blockDim.x)
            if ((i & 1) && b_w[i] != 0) atomicAdd(&nz, 1);
        __syncthreads();
        if (threadIdx.x == 0) g_b64 = (nz == 0) ? 1 : 0;
    }
}

__global__ void zero_kernel(float* __restrict__ dout, int outN, int N) {
    int i = blockIdx.x * blockDim.x + threadIdx.x;
    if (i < N)    { g_degi[i] = 0; g_cursor[i] = 0; }
    if (i < outN) dout[i] = 0.f;
    if (i < FDIM) { g_sum[i] = 0.f; g_sumsq[i] = 0.f; }
}

// Column sums / sums of squares of x (row-major [N,128]); coalesced.
__global__ void col_stats(const float* __restrict__ x, int N) {
    int col = threadIdx.x;  // blockDim = 128
    float s = 0.f, s2 = 0.f;
    for (int r = blockIdx.x; r < N; r += gridDim.x) {
        float v = x[(size_t)r * FDIM + col];
        s += v; s2 += v * v;
    }
    atomicAdd(&g_sum[col], s);
    atomicAdd(&g_sumsq[col], s2);
}

__global__ void deg_count(const void* __restrict__ ei, int E) {
    int e = blockIdx.x * blockDim.x + threadIdx.x;
    if (e < E) {
        int d = load_idx(ei, (long long)E + e, g_ei64);
        atomicAdd(&g_degi[d], 1);
    }
}

__global__ void dinv_kernel(int N) {
    int i = blockIdx.x * blockDim.x + threadIdx.x;
    if (i < N) g_dinv[i] = rsqrtf((float)g_degi[i] + 1.0f);
}

// Fold standardization into W1:  x_std @ W1 = x @ (W1/sigma) + c
__global__ void prep_kernel(const float* __restrict__ W1, int N) {
    __shared__ float mu[FDIM], isd[FDIM];
    int t = threadIdx.x;  // 128 threads
    float sum = g_sum[t];
    float mean = sum / (float)N;
    float var = (g_sumsq[t] - sum * mean) / (float)(N - 1);  // ddof=1
    mu[t] = mean;
    isd[t] = rsqrtf(var);
    __syncthreads();
    float c = 0.f;
    for (int f = 0; f < FDIM; f++) {
        float w = W1[f * FDIM + t];
        g_W1p[f * FDIM + t] = w * isd[f];
        c -= mu[f] * isd[f] * w;
    }
    g_c1[t] = c;
}

// ---------------------------------------------------------------------------
// CSR build: exclusive prefix sum of g_degi -> g_rowp, then bin edges.
__global__ void scan1(int N) {
    __shared__ int sh[256];
    int t = threadIdx.x;
    int base = blockIdx.x * 1024 + t * 4;
    int v[4]; int s = 0;
#pragma unroll
    for (int i = 0; i < 4; i++) {
        v[i] = (base + i < N) ? g_degi[base + i] : 0;
        s += v[i];
    }
    sh[t] = s; __syncthreads();
    for (int off = 1; off < 256; off <<= 1) {
        int x = (t >= off) ? sh[t - off] : 0;
        __syncthreads();
        sh[t] += x;
        __syncthreads();
    }
    int run = sh[t] - s;   // exclusive
    if (t == 255) g_bsum[blockIdx.x] = sh[255];
#pragma unroll
    for (int i = 0; i < 4; i++) {
        if (base + i < N) { g_rowp[base + i] = run; run += v[i]; }
    }
}

__global__ void scan2(int NB) {
    __shared__ int sh[256];
    int t = threadIdx.x;
    int v = (t < NB) ? g_bsum[t] : 0;
    sh[t] = v; __syncthreads();
    for (int off = 1; off < 256; off <<= 1) {
        int x = (t >= off) ? sh[t - off] : 0;
        __syncthreads();
        sh[t] += x;
        __syncthreads();
    }
    if (t < NB) g_boff[t] = sh[t] - v;
}

__global__ void scan3(int N, int E) {
    int i = blockIdx.x * blockDim.x + threadIdx.x;
    if (i < N) g_rowp[i] += g_boff[i >> 10];
    if (i == 0) g_rowp[N] = E;
}

__global__ void bin_edges(const void* __restrict__ ei, int E) {
    int e = blockIdx.x * blockDim.x + threadIdx.x;
    if (e >= E) return;
    int is64 = g_ei64;
    int s = load_idx(ei, e, is64);
    int d = load_idx(ei, (long long)E + e, is64);
    int pos = g_rowp[d] + atomicAdd(&g_cursor[d], 1);
    g_esrc[pos] = s;
    g_ecoef[pos] = g_dinv[s] * g_dinv[d];
}

// ---------------------------------------------------------------------------
// GEMM: C[M,128] = A[M,128] @ B[128,128]  (tf32 wmma, K=128 in padded smem).
// Writes only Cxw (+cvec). RELU_A: relu applied to A on load (layer 2).
template <bool RELU_A, bool ADD_C>
__global__ void gemm_kernel(const float* __restrict__ A, const float* __restrict__ B,
                            const float* __restrict__ cvec,
                            float* __restrict__ Cxw, int M)
{
    extern __shared__ float sB[];  // 128*BPAD floats (reused as epilogue stage)
    for (int i = threadIdx.x; i < FDIM * FDIM; i += blockDim.x) {
        int r = i >> 7, c = i & 127;
        sB[r * BPAD + c] = wmma::__float_to_tf32(B[i]);
    }
    __syncthreads();

    int warp = threadIdx.x >> 5;
    int lane = threadIdx.x & 31;
    int row0 = blockIdx.x * 128 + warp * 16;
    bool active = (row0 + 16) <= M;

    wmma::fragment<wmma::accumulator, 16, 16, 8, float> acc[8];
    if (active) {
#pragma unroll
        for (int n = 0; n < 8; n++) wmma::fill_fragment(acc[n], 0.f);
#pragma unroll
        for (int k = 0; k < FDIM; k += 8) {
            wmma::fragment<wmma::matrix_a, 16, 16, 8, wmma::precision::tf32, wmma::row_major> a;
            wmma::load_matrix_sync(a, A + (size_t)row0 * FDIM + k, FDIM);
#pragma unroll
            for (int t = 0; t < a.num_elements; t++) {
                float v = a.x[t];
                if (RELU_A) v = fmaxf(v, 0.f);
                a.x[t] = wmma::__float_to_tf32(v);
            }
#pragma unroll
            for (int n = 0; n < 8; n++) {
                wmma::fragment<wmma::matrix_b, 16, 16, 8, wmma::precision::tf32, wmma::row_major> b;
                wmma::load_matrix_sync(b, sB + k * BPAD + n * 16, BPAD);
                wmma::mma_sync(acc[n], a, b, acc[n]);
            }
        }
    }
    __syncthreads();
    if (active) {
        float* stage = sB + warp * 16 * BPAD;
#pragma unroll
        for (int n = 0; n < 8; n++)
            wmma::store_matrix_sync(stage + n * 16, acc[n], BPAD, wmma::mem_row_major);
        __syncwarp();
        for (int i = lane; i < 16 * FDIM; i += 32) {
            int r = i >> 7;
            int c = i & 127;
            float v = stage[r * BPAD + c];
            if (ADD_C) v += cvec[c];
            Cxw[(size_t)(row0 + r) * FDIM + c] = v;
        }
    }
}

// ---------------------------------------------------------------------------
__device__ __forceinline__ void red_add_v4(float* p, float4 v) {
    asm volatile("red.global.add.v4.f32 [%0], {%1, %2, %3, %4};"
                 :: "l"(p), "f"(v.x), "f"(v.y), "f"(v.z), "f"(v.w) : "memory");
}

// Atomic-free segmented aggregation: one warp owns one dst node's full row.
//   h[d] = sum_{e in seg(d)} coef[e]*xw[src[e]] + dinv[d]^2*xw[d] + bias
// POOL=false: write h to out[d] (layer 1).
// POOL=true:  out[batch[d]] += relu(h)  (layer 2 fused with global_add_pool).
template <bool POOL>
__global__ void aggregate(const float* __restrict__ xw, float* __restrict__ out,
                          const float* __restrict__ bias,
                          const void* __restrict__ batch, int N)
{
    int node = (int)((blockIdx.x * (unsigned)blockDim.x + threadIdx.x) >> 5);
    int lane = threadIdx.x & 31;
    if (node >= N) return;
    int beg = g_rowp[node];
    int end = g_rowp[node + 1];
    float4 acc = make_float4(0.f, 0.f, 0.f, 0.f);
    for (int e = beg; e < end; e++) {
        int s = g_esrc[e];
        float c = g_ecoef[e];
        float4 v = __ldg((const float4*)(xw + (size_t)s * FDIM) + lane);
        acc.x += c * v.x; acc.y += c * v.y; acc.z += c * v.z; acc.w += c * v.w;
    }
    float di = g_dinv[node];
    float sc = di * di;
    float4 v = ((const float4*)(xw + (size_t)node * FDIM))[lane];
    float4 b = ((const float4*)bias)[lane];
    acc.x += sc * v.x + b.x;
    acc.y += sc * v.y + b.y;
    acc.z += sc * v.z + b.z;
    acc.w += sc * v.w + b.w;
    if (POOL) {
        acc.x = fmaxf(acc.x, 0.f); acc.y = fmaxf(acc.y, 0.f);
        acc.z = fmaxf(acc.z, 0.f); acc.w = fmaxf(acc.w, 0.f);
        int g = load_idx(batch, node, g_b64);
        red_add_v4(out + (size_t)g * FDIM + lane * 4, acc);
    } else {
        ((float4*)(out + (size_t)node * FDIM))[lane] = acc;
    }
}

// ---------------------------------------------------------------------------
extern "C" void kernel_launch(void* const* d_in, const int* in_sizes, int n_in,
                              void* d_out, int out_size)
{
    const float* x     = (const float*)d_in[0];
    const void*  ei    = d_in[1];          // [2,E], int32 or int64 (device-detected)
    const void*  batch = d_in[2];

    int N = in_sizes[0] / FDIM;
    int E = in_sizes[1] / 2;

    const float* wb[4] = {nullptr, nullptr, nullptr, nullptr};
    const int want[4] = {FDIM * FDIM, FDIM, FDIM * FDIM, FDIM};
    int slot = 0;
    for (int i = 3; i < n_in && slot < 4; i++) {
        if (in_sizes[i] <= 2) continue;
        if (in_sizes[i] == want[slot]) wb[slot++] = (const float*)d_in[i];
    }
    if (slot < 4 && n_in >= 7) {
        for (int k = 0; k < 4; k++) wb[k] = (const float*)d_in[n_in - 4 + k];
    }
    const float* W1 = wb[0];
    const float* b1 = wb[1];
    const float* W2 = wb[2];
    const float* b2 = wb[3];

    float* out = (float*)d_out;

    float *p0, *p1, *pW1p, *pc1;
    cudaGetSymbolAddress((void**)&p0,   g_buf0);
    cudaGetSymbolAddress((void**)&p1,   g_buf1);
    cudaGetSymbolAddress((void**)&pW1p, g_W1p);
    cudaGetSymbolAddress((void**)&pc1,  g_c1);

    const int SMEM = FDIM * BPAD * sizeof(float);  // 66 KB (padded)
    cudaFuncSetAttribute(gemm_kernel<false, true>,
                         cudaFuncAttributeMaxDynamicSharedMemorySize, SMEM);
    cudaFuncSetAttribute(gemm_kernel<true, false>,
                         cudaFuncAttributeMaxDynamicSharedMemorySize, SMEM);

    detect_dtype<<<2, 1024>>>((const int*)ei, E, (const int*)batch, N);
    zero_kernel<<<(N + 255) / 256, 256>>>(out, out_size, N);
    col_stats<<<1024, 128>>>(x, N);
    deg_count<<<(E + 255) / 256, 256>>>(ei, E);
    dinv_kernel<<<(N + 255) / 256, 256>>>(N);
    prep_kernel<<<1, 128>>>(W1, N);

    // CSR build
    int NB = (N + 1023) / 1024;
    scan1<<<NB, 256>>>(N);
    scan2<<<1, 256>>>(NB);
    scan3<<<(N + 255) / 256, 256>>>(N, E);
    bin_edges<<<(E + 255) / 256, 256>>>(ei, E);

    int gblocks = (N + 127) / 128;
    int ablocks = (N + 7) / 8;   // 8 warps (nodes) per 256-thread block

    // Layer 1: xw1 = x @ W1' + c1 -> buf0 ; h1 = agg(xw1) + b1 -> buf1
    gemm_kernel<false, true><<<gblocks, 256, SMEM>>>(x, pW1p, pc1, p0, N);
    aggregate<false><<<ablocks, 256>>>(p0, p1, b1, batch, N);

    // Layer 2: xw2 = relu(h1) @ W2 -> buf0 ; out[batch] += relu(agg(xw2) + b2)
    gemm_kernel<true, false><<<gblocks, 256, SMEM>>>(p1, W2, nullptr, p0, N);
    aggregate<true><<<ablocks, 256>>>(p0, out, b2, batch, N);
}